// round 4
// baseline (speedup 1.0000x reference)
#include <cuda_runtime.h>
#include <cstdint>

// LSTMModelClassify: B=2048, T=512, D=1, H=50, C=2, 2-layer LSTM + FC.
// R4: register-resident weights. Thread g (<200) owns gate g completely:
// 150 weights in 78 u64 regs (f32x2-packed, zero-padded to 52/row).
// Gate phase reads ONLY h from smem (warp-broadcast LDS.128).

#define TPB 256
constexpr int NB    = 14;    // batch elems per block
constexpr int Hh    = 50;
constexpr int G4    = 200;   // 4*H
constexpr int Tt    = 512;
constexpr int BATCH = 2048;
constexpr int NC    = 2;
constexpr int W0S   = 52;    // h-state / weight row stride (50 + 2 zero pad)
constexpr int W1S   = 104;   // [Wih1(50)+pad2 | Whh1(50)+pad2]
constexpr int GBS   = 17;    // gate-buffer stride (odd -> conflict-free)

// shared memory layout (floats)
constexpr int OFF_W0   = 0;
constexpr int OFF_W1   = OFF_W0   + G4 * W0S;   // 10400
constexpr int OFF_XS   = OFF_W1   + G4 * W1S;   // 31200
constexpr int OFF_BUFA = OFF_XS   + NB * Tt;    // h1 state [b][52]
constexpr int OFF_BUFB = OFF_BUFA + NB * W0S;   // h2 state [b][52]
constexpr int OFF_GBUF = OFF_BUFB + NB * W0S;   // raw gates [200][17]
constexpr int OFF_B0   = OFF_GBUF + G4 * GBS;
constexpr int OFF_B1   = OFF_B0   + G4;
constexpr int OFF_WX   = OFF_B1   + G4;
constexpr int OFF_WFC  = OFF_WX   + G4;
constexpr int OFF_BFC  = OFF_WFC  + NC * Hh;
constexpr int SMEMF    = OFF_BFC  + NC;         // ~43.9K floats ≈ 176KB

__device__ __forceinline__ unsigned long long ffma2(unsigned long long a,
                                                    unsigned long long b,
                                                    unsigned long long c) {
    unsigned long long d;
    asm("fma.rn.f32x2 %0, %1, %2, %3;" : "=l"(d) : "l"(a), "l"(b), "l"(c));
    return d;
}

__device__ __forceinline__ void unpack2(unsigned long long a, float& x, float& y) {
    unsigned lo, hi;
    asm("mov.b64 {%0, %1}, %2;" : "=r"(lo), "=r"(hi) : "l"(a));
    x = __uint_as_float(lo);
    y = __uint_as_float(hi);
}

__device__ __forceinline__ float sigf(float x) {
    float e = __expf(-x);
    return __fdividef(1.0f, 1.0f + e);
}
__device__ __forceinline__ float tanh_(float x) {
    float e = __expf(2.0f * x);
    return 1.0f - __fdividef(2.0f, 1.0f + e);
}

__global__ void __launch_bounds__(TPB, 1) lstm_kernel(
    const float* __restrict__ x,
    const float* __restrict__ Wih0, const float* __restrict__ Whh0,
    const float* __restrict__ bih0, const float* __restrict__ bhh0,
    const float* __restrict__ Wih1, const float* __restrict__ Whh1,
    const float* __restrict__ bih1, const float* __restrict__ bhh1,
    const float* __restrict__ Wfc,  const float* __restrict__ bfc,
    float* __restrict__ out)
{
    extern __shared__ __align__(16) float sm[];
    const int tid = threadIdx.x;
    const int b0  = blockIdx.x * NB;

    // zero all smem (zero pads + zero initial h states)
    for (int i = tid; i < SMEMF; i += TPB) sm[i] = 0.0f;
    __syncthreads();

    float* W0   = sm + OFF_W0;
    float* W1   = sm + OFF_W1;
    float* xs   = sm + OFF_XS;
    float* bufA = sm + OFF_BUFA;
    float* bufB = sm + OFF_BUFB;
    float* gbuf = sm + OFF_GBUF;
    float* bs0  = sm + OFF_B0;
    float* bs1  = sm + OFF_B1;
    float* wx0  = sm + OFF_WX;
    float* wfc  = sm + OFF_WFC;
    float* bfcs = sm + OFF_BFC;

    // stage weights to smem (one-time)
    for (int i = tid; i < G4 * Hh; i += TPB) {
        int g = i / Hh, k = i % Hh;
        W0[g * W0S + k]      = Whh0[i];
        W1[g * W1S + k]      = Wih1[i];
        W1[g * W1S + 52 + k] = Whh1[i];
    }
    for (int i = tid; i < G4; i += TPB) {
        bs0[i] = bih0[i] + bhh0[i];
        bs1[i] = bih1[i] + bhh1[i];
        wx0[i] = Wih0[i];          // D=1: column vector
    }
    for (int i = tid; i < NB * Tt; i += TPB) {
        int b = i / Tt, t = i % Tt;
        int gb = b0 + b;
        xs[i] = (gb < BATCH) ? x[gb * Tt + t] : 0.0f;
    }
    for (int i = tid; i < NC * Hh; i += TPB) wfc[i] = Wfc[i];
    if (tid < NC) bfcs[tid] = bfc[tid];
    __syncthreads();

    // ---- hoist this thread's gate weights into registers (f32x2 packed) ----
    const int  g    = tid;
    const bool gact = g < G4;
    const int  grow = gact ? g : 0;      // clamp dummies to row 0

    unsigned long long wA[26], wB[26], wC[26];
    {
        const unsigned long long* rA = reinterpret_cast<const unsigned long long*>(W0 + grow * W0S);
        const unsigned long long* rB = reinterpret_cast<const unsigned long long*>(W1 + grow * W1S);
#pragma unroll
        for (int i = 0; i < 26; ++i) { wA[i] = rA[i]; wB[i] = rB[i]; wC[i] = rB[26 + i]; }
    }
    float bg = 0.f, b2g = 0.f, wxg = 0.f;
    if (gact) { bg = bs0[g]; b2g = bs1[g]; wxg = wx0[g]; }
    float* gbr = gbuf + grow * GBS;

    // elementwise role: 700 (j,b) cells per layer across 256 threads
    int  ej[3], eb[3];
    bool eok[3];
    float c1s[3], c2s[3];
#pragma unroll
    for (int i = 0; i < 3; ++i) {
        int u = tid + TPB * i;
        eok[i] = (u < Hh * NB);
        eb[i] = u / Hh;
        ej[i] = u % Hh;
        c1s[i] = 0.f; c2s[i] = 0.f;
    }

    for (int t = 0; t < Tt; ++t) {
        // ---- Layer 1 gates: g = bias + Wih0*x_t + Whh0 @ h1 ----
        {
            unsigned long long a[NB];
#pragma unroll
            for (int b = 0; b < NB; ++b) a[b] = 0ULL;
#pragma unroll
            for (int k4 = 0; k4 < 13; ++k4) {
#pragma unroll
                for (int b = 0; b < NB; ++b) {
                    ulonglong2 hv = *reinterpret_cast<const ulonglong2*>(bufA + b * W0S + 4 * k4);
                    a[b] = ffma2(hv.x, wA[2 * k4],     a[b]);
                    a[b] = ffma2(hv.y, wA[2 * k4 + 1], a[b]);
                }
            }
            if (gact) {
#pragma unroll
                for (int b = 0; b < NB; ++b) {
                    float xv = xs[b * Tt + t];
                    float lo, hi;
                    unpack2(a[b], lo, hi);
                    gbr[b] = lo + hi + fmaf(wxg, xv, bg);
                }
            }
        }
        __syncthreads();

        // ---- Layer 1 elementwise: c1, h1 ----
#pragma unroll
        for (int i = 0; i < 3; ++i) if (eok[i]) {
            int j = ej[i], b = eb[i];
            float gi = gbuf[j * GBS + b];
            float gf = gbuf[(j + 50) * GBS + b];
            float gg = gbuf[(j + 100) * GBS + b];
            float go = gbuf[(j + 150) * GBS + b];
            float cc = sigf(gf) * c1s[i] + sigf(gi) * tanh_(gg);
            c1s[i] = cc;
            bufA[b * W0S + j] = sigf(go) * tanh_(cc);
        }
        __syncthreads();

        // ---- Layer 2 gates: g = bias + Wih1 @ h1_t + Whh1 @ h2_{t-1} ----
        {
            unsigned long long a[NB];
#pragma unroll
            for (int b = 0; b < NB; ++b) a[b] = 0ULL;
#pragma unroll
            for (int k4 = 0; k4 < 13; ++k4) {
#pragma unroll
                for (int b = 0; b < NB; ++b) {
                    ulonglong2 hvA = *reinterpret_cast<const ulonglong2*>(bufA + b * W0S + 4 * k4);
                    ulonglong2 hvB = *reinterpret_cast<const ulonglong2*>(bufB + b * W0S + 4 * k4);
                    a[b] = ffma2(hvA.x, wB[2 * k4],     a[b]);
                    a[b] = ffma2(hvA.y, wB[2 * k4 + 1], a[b]);
                    a[b] = ffma2(hvB.x, wC[2 * k4],     a[b]);
                    a[b] = ffma2(hvB.y, wC[2 * k4 + 1], a[b]);
                }
            }
            if (gact) {
#pragma unroll
                for (int b = 0; b < NB; ++b) {
                    float lo, hi;
                    unpack2(a[b], lo, hi);
                    gbr[b] = lo + hi + b2g;
                }
            }
        }
        __syncthreads();

        // ---- Layer 2 elementwise: c2, h2 ----
#pragma unroll
        for (int i = 0; i < 3; ++i) if (eok[i]) {
            int j = ej[i], b = eb[i];
            float gi = gbuf[j * GBS + b];
            float gf = gbuf[(j + 50) * GBS + b];
            float gg = gbuf[(j + 100) * GBS + b];
            float go = gbuf[(j + 150) * GBS + b];
            float cc = sigf(gf) * c2s[i] + sigf(gi) * tanh_(gg);
            c2s[i] = cc;
            bufB[b * W0S + j] = sigf(go) * tanh_(cc);
        }
        __syncthreads();
    }

    // ---- Final FC on last h2 ----
    if (tid < NB * NC) {
        int bl = tid >> 1;
        int c  = tid & 1;
        int gb = b0 + bl;
        if (gb < BATCH) {
            float s = bfcs[c];
#pragma unroll
            for (int j = 0; j < Hh; ++j) s += wfc[c * Hh + j] * bufB[bl * W0S + j];
            out[gb * NC + c] = s;
        }
    }
}

extern "C" void kernel_launch(void* const* d_in, const int* in_sizes, int n_in,
                              void* d_out, int out_size) {
    const float* x    = (const float*)d_in[0];
    const float* Wih0 = (const float*)d_in[1];
    const float* Whh0 = (const float*)d_in[2];
    const float* bih0 = (const float*)d_in[3];
    const float* bhh0 = (const float*)d_in[4];
    const float* Wih1 = (const float*)d_in[5];
    const float* Whh1 = (const float*)d_in[6];
    const float* bih1 = (const float*)d_in[7];
    const float* bhh1 = (const float*)d_in[8];
    const float* Wfc  = (const float*)d_in[9];
    const float* bfc  = (const float*)d_in[10];
    float* out = (float*)d_out;

    const int smem_bytes = SMEMF * (int)sizeof(float);
    cudaFuncSetAttribute(lstm_kernel, cudaFuncAttributeMaxDynamicSharedMemorySize, smem_bytes);

    const int grid = (BATCH + NB - 1) / NB;   // 147 blocks, one wave
    lstm_kernel<<<grid, TPB, smem_bytes>>>(x, Wih0, Whh0, bih0, bhh0,
                                           Wih1, Whh1, bih1, bhh1,
                                           Wfc, bfc, out);
}